// round 1
// baseline (speedup 1.0000x reference)
#include <cuda_runtime.h>
#include <cstdint>

// UpsampleLayer2D quadrant depth-to-space:
// out[b, r2, c2, co] = x[b, r2%R, c2%C, 4*co + k],  k = 2*(r2>=R) + (c2>=C)
// B=32, R=C=200, Cin=64, Co=16.
//
// float4 view of input: x4[pix*16 + co] = (k0, k1, k2, k3) quadrant values for
// output channel co of that pixel. Each thread handles one pixel and a group of
// 4 output channels (co4*4 .. co4*4+3): load 4 consecutive float4 (64B,
// warp-contiguous), 4x4 register transpose, store one float4 per quadrant
// (each warp's stores are 512B contiguous per quadrant).

static constexpr int B  = 32;
static constexpr int R  = 200;
static constexpr int C  = 200;
static constexpr int CO = 16;            // output channels
static constexpr unsigned PIX = B * R * C;          // 1,280,000 pixels
static constexpr unsigned NTHREADS = PIX * 4;       // 5,120,000 (co groups of 4)

// float4 strides in the output [B, 2R, 2C, CO]:
static constexpr size_t OUT_ROW_F4  = (size_t)(2 * C) * CO / 4;   // 1600
static constexpr size_t Q_COL_OFF   = (size_t)C * CO / 4;         // +200 cols   = 800
static constexpr size_t Q_ROW_OFF   = (size_t)R * OUT_ROW_F4;     // +200 rows   = 320000

__global__ __launch_bounds__(256) void upsample2d_kernel(
    const float4* __restrict__ x4, float4* __restrict__ out4)
{
    unsigned g = blockIdx.x * 256u + threadIdx.x;   // grid sized exactly
    unsigned co4 = g & 3u;          // which group of 4 output channels
    unsigned pix = g >> 2;          // input pixel index

    unsigned c  = pix % (unsigned)C;
    unsigned rb = pix / (unsigned)C;
    unsigned r  = rb % (unsigned)R;
    unsigned b  = rb / (unsigned)R;

    const float4* src = x4 + (size_t)pix * 16 + (size_t)co4 * 4;
    float4 v0 = src[0];
    float4 v1 = src[1];
    float4 v2 = src[2];
    float4 v3 = src[3];

    size_t opix = ((size_t)b * (2 * R) + r) * (2 * C) + c;  // quadrant-0 pixel
    size_t o0   = opix * 4 + co4;                            // float4 index

    out4[o0]                       = make_float4(v0.x, v1.x, v2.x, v3.x); // k=0: TL
    out4[o0 + Q_COL_OFF]           = make_float4(v0.y, v1.y, v2.y, v3.y); // k=1: TR
    out4[o0 + Q_ROW_OFF]           = make_float4(v0.z, v1.z, v2.z, v3.z); // k=2: BL
    out4[o0 + Q_ROW_OFF + Q_COL_OFF] = make_float4(v0.w, v1.w, v2.w, v3.w); // k=3: BR
}

extern "C" void kernel_launch(void* const* d_in, const int* in_sizes, int n_in,
                              void* d_out, int out_size)
{
    const float4* x4   = (const float4*)d_in[0];
    float4*       out4 = (float4*)d_out;

    // NTHREADS = 5,120,000 = 20000 * 256 exactly; no bounds check needed.
    upsample2d_kernel<<<NTHREADS / 256, 256>>>(x4, out4);
}

// round 2
// speedup vs baseline: 1.0055x; 1.0055x over previous
#include <cuda_runtime.h>
#include <cstdint>

// UpsampleLayer2D quadrant depth-to-space:
// out[b, r2, c2, co] = x[b, r2%R, c2%C, 4*co + k],  k = 2*(r2>=R) + (c2>=C)
// B=32, R=C=200, Cin=64, Co=16.
//
// R1: added streaming cache hints (__ldcs/__stcs). Both tensors are ~328MB,
// touch-once, >> 126MB L2 — evict-first keeps L2 from thrashing between the
// read stream and the 4 write streams.

static constexpr int B  = 32;
static constexpr int R  = 200;
static constexpr int C  = 200;
static constexpr int CO = 16;            // output channels
static constexpr unsigned PIX = B * R * C;          // 1,280,000 pixels
static constexpr unsigned NTHREADS = PIX * 4;       // 5,120,000 (co groups of 4)

// float4 strides in the output [B, 2R, 2C, CO]:
static constexpr size_t OUT_ROW_F4  = (size_t)(2 * C) * CO / 4;   // 1600
static constexpr size_t Q_COL_OFF   = (size_t)C * CO / 4;         // 800
static constexpr size_t Q_ROW_OFF   = (size_t)R * OUT_ROW_F4;     // 320000

__global__ __launch_bounds__(512) void upsample2d_kernel(
    const float4* __restrict__ x4, float4* __restrict__ out4)
{
    unsigned g = blockIdx.x * 512u + threadIdx.x;   // grid sized exactly
    unsigned co4 = g & 3u;          // which group of 4 output channels
    unsigned pix = g >> 2;          // input pixel index

    unsigned c  = pix % (unsigned)C;
    unsigned rb = pix / (unsigned)C;
    unsigned r  = rb % (unsigned)R;
    unsigned b  = rb / (unsigned)R;

    const float4* src = x4 + (size_t)pix * 16 + (size_t)co4 * 4;
    float4 v0 = __ldcs(src + 0);
    float4 v1 = __ldcs(src + 1);
    float4 v2 = __ldcs(src + 2);
    float4 v3 = __ldcs(src + 3);

    size_t opix = ((size_t)b * (2 * R) + r) * (2 * C) + c;  // quadrant-0 pixel
    size_t o0   = opix * 4 + co4;                            // float4 index

    __stcs(out4 + o0,                         make_float4(v0.x, v1.x, v2.x, v3.x)); // TL
    __stcs(out4 + o0 + Q_COL_OFF,             make_float4(v0.y, v1.y, v2.y, v3.y)); // TR
    __stcs(out4 + o0 + Q_ROW_OFF,             make_float4(v0.z, v1.z, v2.z, v3.z)); // BL
    __stcs(out4 + o0 + Q_ROW_OFF + Q_COL_OFF, make_float4(v0.w, v1.w, v2.w, v3.w)); // BR
}

extern "C" void kernel_launch(void* const* d_in, const int* in_sizes, int n_in,
                              void* d_out, int out_size)
{
    const float4* x4   = (const float4*)d_in[0];
    float4*       out4 = (float4*)d_out;

    // NTHREADS = 5,120,000 = 10000 * 512 exactly; no bounds check needed.
    upsample2d_kernel<<<NTHREADS / 512, 512>>>(x4, out4);
}